// round 13
// baseline (speedup 1.0000x reference)
#include <cuda_runtime.h>
#include <cuda_bf16.h>
#include <mma.h>
#include <math.h>
#include <stdint.h>

using namespace nvcuda;

#define IN_DIM 512
#define HID    128
#define MAXN   50176
#define MAXE   800000
#define SCAN_BLK 1024

// -------------------- device-global scratch --------------------
__device__ float g_h[(size_t)MAXN * 128];   // GEMM output
__device__ float g_x[(size_t)MAXN * 128];   // aggregated activations
__device__ float g_dis[MAXN];
__device__ int   g_deg[MAXN];
__device__ int   g_off[MAXN + 1];
__device__ int   g_slot[MAXE];
__device__ int   g_csr[MAXE];
__device__ int   g_bsum[64];
__device__ int   g_boff[64];
// pre-split weights, bf16, [K,F] row-major (hi + lo)
__device__ __nv_bfloat16 g_w1h[512 * 128], g_w1l[512 * 128];
__device__ __nv_bfloat16 g_w2h[128 * 128], g_w2l[128 * 128];
__device__ __nv_bfloat16 g_w3h[128 * 64],  g_w3l[128 * 64];

// -------------------- graph preprocessing --------------------
__global__ void init_deg(int n) {
    int i = blockIdx.x * blockDim.x + threadIdx.x;
    if (i < n) g_deg[i] = 1;  // self loop
}
__global__ void count_deg(const int* __restrict__ dst, int e, int n) {
    int i = blockIdx.x * blockDim.x + threadIdx.x;
    if (i < e) {
        int d = dst[i];
        if ((unsigned)d < (unsigned)n) {
            int old = atomicAdd(&g_deg[d], 1);
            g_slot[i] = old - 1;
        }
    }
}
__global__ void scan_partial(int n) {
    __shared__ int s[SCAN_BLK];
    int b = blockIdx.x, tid = threadIdx.x;
    int i = b * SCAN_BLK + tid;
    int v = (i < n) ? (g_deg[i] - 1) : 0;
    s[tid] = v;
    __syncthreads();
    #pragma unroll
    for (int o = 1; o < SCAN_BLK; o <<= 1) {
        int t = (tid >= o) ? s[tid - o] : 0;
        __syncthreads();
        s[tid] += t;
        __syncthreads();
    }
    if (i < n) g_off[i] = s[tid] - v;
    if (tid == SCAN_BLK - 1) g_bsum[b] = s[tid];
}
__global__ void scan_bsum(int nb, int n) {
    __shared__ int s[64];
    int tid = threadIdx.x;
    int v = (tid < nb) ? g_bsum[tid] : 0;
    s[tid] = v;
    __syncthreads();
    #pragma unroll
    for (int o = 1; o < 64; o <<= 1) {
        int t = (tid >= o) ? s[tid - o] : 0;
        __syncthreads();
        s[tid] += t;
        __syncthreads();
    }
    if (tid < nb) g_boff[tid] = s[tid] - v;
    if (tid == 63) g_off[n] = s[63];
}
__global__ void add_off_dis(int n) {
    int i = blockIdx.x * blockDim.x + threadIdx.x;
    if (i < n) {
        g_off[i] += g_boff[i >> 10];
        g_dis[i] = rsqrtf((float)g_deg[i]);
    }
}
__global__ void fill_csr(const int* __restrict__ src,
                         const int* __restrict__ dst, int e, int n) {
    int i = blockIdx.x * blockDim.x + threadIdx.x;
    if (i < e) {
        int d = dst[i];
        int s = src[i];
        if ((unsigned)d < (unsigned)n && (unsigned)s < (unsigned)n) {
            int pos = g_off[d] + g_slot[i];
            if ((unsigned)pos < (unsigned)MAXE) g_csr[pos] = s;
        }
    }
}

// -------------------- weight split (fp32 -> bf16 hi + lo), [K,F] kept --------
__global__ void wsplit(const float* __restrict__ W, int KF, int sel) {
    int i = blockIdx.x * blockDim.x + threadIdx.x;
    if (i >= KF) return;
    float x = W[i];
    __nv_bfloat16 h = __float2bfloat16_rn(x);
    float l = x - __bfloat162float(h);
    __nv_bfloat16* Wh = (sel == 0) ? g_w1h : (sel == 1) ? g_w2h : g_w3h;
    __nv_bfloat16* Wl = (sel == 0) ? g_w1l : (sel == 1) ? g_w2l : g_w3l;
    Wh[i] = h;
    Wl[i] = __float2bfloat16_rn(l);
}

// -------------------- cp.async helper --------------------
__device__ __forceinline__ void cpa16(void* sdst, const void* gsrc) {
    uint32_t sa = (uint32_t)__cvta_generic_to_shared(sdst);
    asm volatile("cp.async.cg.shared.global [%0], [%1], 16;\n"
                 :: "r"(sa), "l"(gsrc));
}
#define CPA_COMMIT() asm volatile("cp.async.commit_group;\n" ::: "memory")
#define CPA_WAIT0()  asm volatile("cp.async.wait_group 0;\n" ::: "memory")

// -------------------- WMMA bf16 split GEMM, 64xBN tile, 128 thr, 4 CTAs/SM --
// g_h[n,BN] = X[n,K] @ W[K,BN], D = Ahi*Bhi + Ahi*Blo + Alo*Bhi (fp32 accum).
// 4 warps = 2 M-warps x 2 N-warps, warp tile 32 x (BN/2): per ks-step 12
// fragment loads per 24 wmma (best economy) at 4 CTAs/SM occupancy.
template <int BN>
__global__ void __launch_bounds__(128, 4)
wgemm(const float* __restrict__ Xext, int use_gx, int wsel, int n, int K) {
    constexpr int LDA = 40;        // 32 + 8 pad (bf16 elems)
    constexpr int LDB = BN + 8;
    constexpr int WN  = BN / 2;    // 64 or 32
    constexpr int JT  = WN / 16;   // 4 or 2
    constexpr int ASZ = 64 * LDA;
    constexpr int BSZ = 32 * LDB;

    extern __shared__ __nv_bfloat16 smem[];
    __nv_bfloat16* Ah = smem;
    __nv_bfloat16* Al = smem + 2 * ASZ;
    __nv_bfloat16* Bh = smem + 4 * ASZ;
    __nv_bfloat16* Bl = smem + 4 * ASZ + 2 * BSZ;

    const float* __restrict__ X = use_gx ? (const float*)g_x : Xext;
    const __nv_bfloat16* __restrict__ Wh =
        (wsel == 0) ? g_w1h : (wsel == 1) ? g_w2h : g_w3h;
    const __nv_bfloat16* __restrict__ Wl =
        (wsel == 0) ? g_w1l : (wsel == 1) ? g_w2l : g_w3l;

    const int tid = threadIdx.x;
    const int wid = tid >> 5;
    const int wm = wid & 1;        // 2 M-warp rows
    const int wn = wid >> 1;       // 2 N-warp cols
    const int row0 = blockIdx.x * 64;

    wmma::fragment<wmma::accumulator, 16, 16, 16, float> acc[2][JT];
    #pragma unroll
    for (int i = 0; i < 2; i++)
        #pragma unroll
        for (int j = 0; j < JT; j++) wmma::fill_fragment(acc[i][j], 0.0f);

    const float4 z4 = make_float4(0.f, 0.f, 0.f, 0.f);

    // A: 64x32 f32 = 512 float4 -> 4 per thread (128 thr)
    auto ldgA = [&](int k0, float4* pa) {
        #pragma unroll
        for (int p = 0; p < 4; p++) {
            int f = tid + p * 128;
            int r = f >> 3, c = f & 7;
            int gr = row0 + r;
            pa[p] = (gr < n) ? *(const float4*)(X + (size_t)gr * K + k0 + c * 4)
                             : z4;
        }
    };
    auto stsA = [&](int st, const float4* pa) {
        #pragma unroll
        for (int p = 0; p < 4; p++) {
            int f = tid + p * 128;
            int r = f >> 3, c = f & 7;
            float4 v = pa[p];
            __nv_bfloat16 h0 = __float2bfloat16_rn(v.x);
            __nv_bfloat16 h1 = __float2bfloat16_rn(v.y);
            __nv_bfloat16 h2 = __float2bfloat16_rn(v.z);
            __nv_bfloat16 h3 = __float2bfloat16_rn(v.w);
            __nv_bfloat162 hp0 = __nv_bfloat162(h0, h1);
            __nv_bfloat162 hp1 = __nv_bfloat162(h2, h3);
            __nv_bfloat162 lp0 = __nv_bfloat162(
                __float2bfloat16_rn(v.x - __bfloat162float(h0)),
                __float2bfloat16_rn(v.y - __bfloat162float(h1)));
            __nv_bfloat162 lp1 = __nv_bfloat162(
                __float2bfloat16_rn(v.z - __bfloat162float(h2)),
                __float2bfloat16_rn(v.w - __bfloat162float(h3)));
            uint2 hw, lw;
            hw.x = *(uint32_t*)&hp0; hw.y = *(uint32_t*)&hp1;
            lw.x = *(uint32_t*)&lp0; lw.y = *(uint32_t*)&lp1;
            *(uint2*)&Ah[st * ASZ + r * LDA + c * 4] = hw;
            *(uint2*)&Al[st * ASZ + r * LDA + c * 4] = lw;
        }
    };
    auto cpaB = [&](int st, int k0) {
        if (BN == 128) {
            // 32x128 bf16 = 512 uint4 -> 4 per thread
            #pragma unroll
            for (int p = 0; p < 4; p++) {
                int idx = tid + p * 128;
                int r = idx >> 4, c8 = idx & 15;
                cpa16(&Bh[st * BSZ + r * LDB + c8 * 8],
                      Wh + (size_t)(k0 + r) * BN + c8 * 8);
                cpa16(&Bl[st * BSZ + r * LDB + c8 * 8],
                      Wl + (size_t)(k0 + r) * BN + c8 * 8);
            }
        } else {
            // 32x64 bf16 = 256 uint4 -> 2 per thread
            #pragma unroll
            for (int p = 0; p < 2; p++) {
                int idx = tid + p * 128;
                int r = idx >> 3, c8 = idx & 7;
                cpa16(&Bh[st * BSZ + r * LDB + c8 * 8],
                      Wh + (size_t)(k0 + r) * BN + c8 * 8);
                cpa16(&Bl[st * BSZ + r * LDB + c8 * 8],
                      Wl + (size_t)(k0 + r) * BN + c8 * 8);
            }
        }
        CPA_COMMIT();
    };

    float4 pa[4];
    ldgA(0, pa);
    cpaB(0, 0);
    stsA(0, pa);
    CPA_WAIT0();
    __syncthreads();

    const int T = K >> 5;
    for (int t = 0; t < T; t++) {
        const int cur = t & 1, nxt = cur ^ 1;
        const bool more = (t + 1 < T);
        if (more) {
            cpaB(nxt, (t + 1) << 5);
            ldgA((t + 1) << 5, pa);
        }

        #pragma unroll
        for (int ks = 0; ks < 2; ks++) {
            wmma::fragment<wmma::matrix_a, 16, 16, 16, __nv_bfloat16,
                           wmma::row_major> ah[2], al[2];
            #pragma unroll
            for (int i = 0; i < 2; i++) {
                wmma::load_matrix_sync(ah[i],
                    &Ah[cur * ASZ + (wm * 32 + i * 16) * LDA + ks * 16], LDA);
                wmma::load_matrix_sync(al[i],
                    &Al[cur * ASZ + (wm * 32 + i * 16) * LDA + ks * 16], LDA);
            }
            #pragma unroll
            for (int j = 0; j < JT; j++) {
                wmma::fragment<wmma::matrix_b, 16, 16, 16, __nv_bfloat16,
                               wmma::row_major> bh, bl;
                wmma::load_matrix_sync(bh,
                    &Bh[cur * BSZ + ks * 16 * LDB + wn * WN + j * 16], LDB);
                wmma::load_matrix_sync(bl,
                    &Bl[cur * BSZ + ks * 16 * LDB + wn * WN + j * 16], LDB);
                wmma::mma_sync(acc[0][j], ah[0], bh, acc[0][j]);
                wmma::mma_sync(acc[1][j], ah[1], bh, acc[1][j]);
                wmma::mma_sync(acc[0][j], ah[0], bl, acc[0][j]);
                wmma::mma_sync(acc[1][j], ah[1], bl, acc[1][j]);
                wmma::mma_sync(acc[0][j], al[0], bh, acc[0][j]);
                wmma::mma_sync(acc[1][j], al[1], bh, acc[1][j]);
            }
        }

        if (more) {
            stsA(nxt, pa);
            CPA_WAIT0();
        }
        __syncthreads();
    }

    #pragma unroll
    for (int i = 0; i < 2; i++) {
        int r = row0 + wm * 32 + i * 16;
        #pragma unroll
        for (int j = 0; j < JT; j++) {
            int c = wn * WN + j * 16;
            wmma::store_matrix_sync(&g_h[(size_t)r * BN + c], acc[i][j], BN,
                                    wmma::mem_row_major);
        }
    }
}

// -------------------- aggregation: one warp per node, float4 per lane -------
__global__ void agg128_relu(const float* __restrict__ bias, int n) {
    int node = (blockIdx.x * blockDim.x + threadIdx.x) >> 5;
    int lane = threadIdx.x & 31;
    if (node >= n) return;
    const float4* __restrict__ h4 = (const float4*)g_h;
    float4 b4 = ((const float4*)bias)[lane];
    float dn = g_dis[node];
    float4 hv = h4[(size_t)node * 32 + lane];
    float4 acc = make_float4(dn * hv.x, dn * hv.y, dn * hv.z, dn * hv.w);

    int j = g_off[node], end = g_off[node + 1];
    for (; j + 3 < end; j += 4) {
        int s0 = g_csr[j],     s1 = g_csr[j + 1];
        int s2 = g_csr[j + 2], s3 = g_csr[j + 3];
        float d0 = g_dis[s0], d1 = g_dis[s1], d2 = g_dis[s2], d3 = g_dis[s3];
        float4 v0 = h4[(size_t)s0 * 32 + lane];
        float4 v1 = h4[(size_t)s1 * 32 + lane];
        float4 v2 = h4[(size_t)s2 * 32 + lane];
        float4 v3 = h4[(size_t)s3 * 32 + lane];
        acc.x = fmaf(d0, v0.x, acc.x); acc.y = fmaf(d0, v0.y, acc.y);
        acc.z = fmaf(d0, v0.z, acc.z); acc.w = fmaf(d0, v0.w, acc.w);
        acc.x = fmaf(d1, v1.x, acc.x); acc.y = fmaf(d1, v1.y, acc.y);
        acc.z = fmaf(d1, v1.z, acc.z); acc.w = fmaf(d1, v1.w, acc.w);
        acc.x = fmaf(d2, v2.x, acc.x); acc.y = fmaf(d2, v2.y, acc.y);
        acc.z = fmaf(d2, v2.z, acc.z); acc.w = fmaf(d2, v2.w, acc.w);
        acc.x = fmaf(d3, v3.x, acc.x); acc.y = fmaf(d3, v3.y, acc.y);
        acc.z = fmaf(d3, v3.z, acc.z); acc.w = fmaf(d3, v3.w, acc.w);
    }
    for (; j < end; ++j) {
        int s0 = g_csr[j];
        float d0 = g_dis[s0];
        float4 v0 = h4[(size_t)s0 * 32 + lane];
        acc.x = fmaf(d0, v0.x, acc.x); acc.y = fmaf(d0, v0.y, acc.y);
        acc.z = fmaf(d0, v0.z, acc.z); acc.w = fmaf(d0, v0.w, acc.w);
    }
    float4 r;
    r.x = fmaxf(fmaf(dn, acc.x, b4.x), 0.f);
    r.y = fmaxf(fmaf(dn, acc.y, b4.y), 0.f);
    r.z = fmaxf(fmaf(dn, acc.z, b4.z), 0.f);
    r.w = fmaxf(fmaf(dn, acc.w, b4.w), 0.f);
    ((float4*)g_x)[(size_t)node * 32 + lane] = r;
}

// layer-3 agg + log_softmax: one warp per node, float2 per lane (64 feats)
__global__ void agg64_lsm(const float* __restrict__ bias,
                          float* __restrict__ out, int n) {
    int node = (blockIdx.x * blockDim.x + threadIdx.x) >> 5;
    int lane = threadIdx.x & 31;
    if (node >= n) return;
    const float2* __restrict__ h2 = (const float2*)g_h;
    float2 b2 = ((const float2*)bias)[lane];
    float dn = g_dis[node];
    float2 hv = h2[(size_t)node * 32 + lane];
    float ax = dn * hv.x, ay = dn * hv.y;

    int j = g_off[node], end = g_off[node + 1];
    for (; j + 3 < end; j += 4) {
        int s0 = g_csr[j],     s1 = g_csr[j + 1];
        int s2 = g_csr[j + 2], s3 = g_csr[j + 3];
        float d0 = g_dis[s0], d1 = g_dis[s1], d2 = g_dis[s2], d3 = g_dis[s3];
        float2 v0 = h2[(size_t)s0 * 32 + lane];
        float2 v1 = h2[(size_t)s1 * 32 + lane];
        float2 v2 = h2[(size_t)s2 * 32 + lane];
        float2 v3 = h2[(size_t)s3 * 32 + lane];
        ax = fmaf(d0, v0.x, ax); ay = fmaf(d0, v0.y, ay);
        ax = fmaf(d1, v1.x, ax); ay = fmaf(d1, v1.y, ay);
        ax = fmaf(d2, v2.x, ax); ay = fmaf(d2, v2.y, ay);
        ax = fmaf(d3, v3.x, ax); ay = fmaf(d3, v3.y, ay);
    }
    for (; j < end; ++j) {
        int s0 = g_csr[j];
        float d0 = g_dis[s0];
        float2 v0 = h2[(size_t)s0 * 32 + lane];
        ax = fmaf(d0, v0.x, ax); ay = fmaf(d0, v0.y, ay);
    }
    float v0 = fmaf(dn, ax, b2.x);
    float v1 = fmaf(dn, ay, b2.y);

    float m = fmaxf(v0, v1);
    #pragma unroll
    for (int o = 16; o; o >>= 1) m = fmaxf(m, __shfl_xor_sync(0xffffffffu, m, o));
    float s = expf(v0 - m) + expf(v1 - m);
    #pragma unroll
    for (int o = 16; o; o >>= 1) s += __shfl_xor_sync(0xffffffffu, s, o);
    float l = m + logf(s);
    float2 r = make_float2(v0 - l, v1 - l);
    ((float2*)out)[(size_t)node * 32 + lane] = r;
}

// -------------------- launch --------------------
extern "C" void kernel_launch(void* const* d_in, const int* in_sizes, int n_in,
                              void* d_out, int out_size) {
    const float* feats = (const float*)d_in[0];
    const int*   adj   = (const int*)d_in[1];     // int32 (jax x64 disabled)
    const float* W1    = (const float*)d_in[2];
    const float* b1    = (const float*)d_in[3];
    const float* W2    = (const float*)d_in[4];
    const float* b2    = (const float*)d_in[5];
    const float* W3    = (const float*)d_in[6];
    const float* b3    = (const float*)d_in[7];
    float*       out   = (float*)d_out;

    const int N = in_sizes[0] / IN_DIM;
    const int E = in_sizes[1] / 2;
    const int* src = adj;
    const int* dst = adj + E;
    const int nb = (N + SCAN_BLK - 1) / SCAN_BLK;
    const int gB = (N + 63) / 64;

    // dynamic smem (2 stages of Ah/Al 64x40 + Bh/Bl 32xLDB)
    const int smem128 = (4 * 64 * 40 + 4 * 32 * 136) * 2;  // 55296 B
    const int smem64  = (4 * 64 * 40 + 4 * 32 * 72) * 2;   // 38912 B
    cudaFuncSetAttribute(wgemm<128>, cudaFuncAttributeMaxDynamicSharedMemorySize, smem128);
    cudaFuncSetAttribute(wgemm<64>,  cudaFuncAttributeMaxDynamicSharedMemorySize, smem64);

    static cudaStream_t s2 = nullptr;
    static cudaEvent_t evFork = nullptr, evJoin = nullptr;
    if (s2 == nullptr) {
        cudaStreamCreateWithFlags(&s2, cudaStreamNonBlocking);
        cudaEventCreateWithFlags(&evFork, cudaEventDisableTiming);
        cudaEventCreateWithFlags(&evJoin, cudaEventDisableTiming);
    }

    // ---- launch 1: W1 split (needed by GEMM1) ----
    wsplit<<<(IN_DIM * HID + 255) / 256, 256>>>(W1, IN_DIM * HID, 0);
    // ---- fork side stream: W2/W3 splits + graph preprocessing ----
    cudaEventRecord(evFork, 0);
    cudaStreamWaitEvent(s2, evFork, 0);
    wsplit<<<(HID * HID + 255) / 256, 256, 0, s2>>>(W2, HID * HID, 1);   // 2
    wsplit<<<(HID * 64 + 255) / 256, 256, 0, s2>>>(W3, HID * 64, 2);     // 3
    // ---- launch 4 (profiled slot): GEMM1 on main stream ----
    wgemm<128><<<gB, 128, smem128>>>(feats, 0, 0, N, IN_DIM);

    init_deg<<<(N + 255) / 256, 256, 0, s2>>>(N);
    count_deg<<<(E + 255) / 256, 256, 0, s2>>>(dst, E, N);
    scan_partial<<<nb, SCAN_BLK, 0, s2>>>(N);
    scan_bsum<<<1, 64, 0, s2>>>(nb, N);
    add_off_dis<<<(N + 255) / 256, 256, 0, s2>>>(N);
    fill_csr<<<(E + 255) / 256, 256, 0, s2>>>(src, dst, E, N);
    cudaEventRecord(evJoin, s2);
    cudaStreamWaitEvent(0, evJoin, 0);   // join before aggregation

    // ---- layers (main stream) ----
    agg128_relu<<<(N + 7) / 8, 256>>>(b1, N);
    wgemm<128><<<gB, 128, smem128>>>(nullptr, 1, 1, N, HID);
    agg128_relu<<<(N + 7) / 8, 256>>>(b2, N);
    wgemm<64><<<gB, 128, smem64>>>(nullptr, 1, 2, N, HID);
    agg64_lsm<<<(N + 7) / 8, 256>>>(b3, out, N);
}

// round 14
// speedup vs baseline: 1.0205x; 1.0205x over previous
#include <cuda_runtime.h>
#include <cuda_bf16.h>
#include <mma.h>
#include <math.h>
#include <stdint.h>

using namespace nvcuda;

#define IN_DIM 512
#define HID    128
#define MAXN   50176
#define MAXE   800000
#define SCAN_BLK 1024

// -------------------- device-global scratch --------------------
__device__ float g_h[(size_t)MAXN * 128];             // GEMM output (fp32)
__device__ __nv_bfloat16 g_xh[(size_t)MAXN * 128];    // activations hi (bf16)
__device__ __nv_bfloat16 g_xl[(size_t)MAXN * 128];    // activations lo (bf16)
__device__ float g_dis[MAXN];
__device__ int   g_deg[MAXN];
__device__ int   g_off[MAXN + 1];
__device__ int   g_slot[MAXE];
__device__ int   g_csr[MAXE];
__device__ int   g_bsum[64];
__device__ int   g_boff[64];
// pre-split weights, bf16, [K,F] row-major (hi + lo)
__device__ __nv_bfloat16 g_w1h[512 * 128], g_w1l[512 * 128];
__device__ __nv_bfloat16 g_w2h[128 * 128], g_w2l[128 * 128];
__device__ __nv_bfloat16 g_w3h[128 * 64],  g_w3l[128 * 64];

// -------------------- graph preprocessing --------------------
__global__ void init_deg(int n) {
    int i = blockIdx.x * blockDim.x + threadIdx.x;
    if (i < n) g_deg[i] = 1;  // self loop
}
__global__ void count_deg(const int* __restrict__ dst, int e, int n) {
    int i = blockIdx.x * blockDim.x + threadIdx.x;
    if (i < e) {
        int d = dst[i];
        if ((unsigned)d < (unsigned)n) {
            int old = atomicAdd(&g_deg[d], 1);
            g_slot[i] = old - 1;
        }
    }
}
__global__ void scan_partial(int n) {
    __shared__ int s[SCAN_BLK];
    int b = blockIdx.x, tid = threadIdx.x;
    int i = b * SCAN_BLK + tid;
    int v = (i < n) ? (g_deg[i] - 1) : 0;
    s[tid] = v;
    __syncthreads();
    #pragma unroll
    for (int o = 1; o < SCAN_BLK; o <<= 1) {
        int t = (tid >= o) ? s[tid - o] : 0;
        __syncthreads();
        s[tid] += t;
        __syncthreads();
    }
    if (i < n) g_off[i] = s[tid] - v;
    if (tid == SCAN_BLK - 1) g_bsum[b] = s[tid];
}
__global__ void scan_bsum(int nb, int n) {
    __shared__ int s[64];
    int tid = threadIdx.x;
    int v = (tid < nb) ? g_bsum[tid] : 0;
    s[tid] = v;
    __syncthreads();
    #pragma unroll
    for (int o = 1; o < 64; o <<= 1) {
        int t = (tid >= o) ? s[tid - o] : 0;
        __syncthreads();
        s[tid] += t;
        __syncthreads();
    }
    if (tid < nb) g_boff[tid] = s[tid] - v;
    if (tid == 63) g_off[n] = s[63];
}
__global__ void add_off_dis(int n) {
    int i = blockIdx.x * blockDim.x + threadIdx.x;
    if (i < n) {
        g_off[i] += g_boff[i >> 10];
        g_dis[i] = rsqrtf((float)g_deg[i]);
    }
}
__global__ void fill_csr(const int* __restrict__ src,
                         const int* __restrict__ dst, int e, int n) {
    int i = blockIdx.x * blockDim.x + threadIdx.x;
    if (i < e) {
        int d = dst[i];
        int s = src[i];
        if ((unsigned)d < (unsigned)n && (unsigned)s < (unsigned)n) {
            int pos = g_off[d] + g_slot[i];
            if ((unsigned)pos < (unsigned)MAXE) g_csr[pos] = s;
        }
    }
}

// -------------------- weight split (fp32 -> bf16 hi + lo), [K,F] kept --------
__global__ void wsplit(const float* __restrict__ W, int KF, int sel) {
    int i = blockIdx.x * blockDim.x + threadIdx.x;
    if (i >= KF) return;
    float x = W[i];
    __nv_bfloat16 h = __float2bfloat16_rn(x);
    float l = x - __bfloat162float(h);
    __nv_bfloat16* Wh = (sel == 0) ? g_w1h : (sel == 1) ? g_w2h : g_w3h;
    __nv_bfloat16* Wl = (sel == 0) ? g_w1l : (sel == 1) ? g_w2l : g_w3l;
    Wh[i] = h;
    Wl[i] = __float2bfloat16_rn(l);
}

// -------------------- cp.async helper --------------------
__device__ __forceinline__ void cpa16(void* sdst, const void* gsrc) {
    uint32_t sa = (uint32_t)__cvta_generic_to_shared(sdst);
    asm volatile("cp.async.cg.shared.global [%0], [%1], 16;\n"
                 :: "r"(sa), "l"(gsrc));
}
#define CPA_COMMIT() asm volatile("cp.async.commit_group;\n" ::: "memory")
#define CPA_WAIT0()  asm volatile("cp.async.wait_group 0;\n" ::: "memory")

// -------------------- GEMM1: fp32 input, on-the-fly split (R12 config) ------
// g_h[n,128] = X[n,K] @ W1[K,128]. 64x128 tile, 256 thr (2Mx4N warps), 3 CTA/SM.
__global__ void __launch_bounds__(256, 3)
wgemm1(const float* __restrict__ X, int n, int K) {
    constexpr int BN = 128;
    constexpr int LDA = 40;
    constexpr int LDB = BN + 8;
    constexpr int WN  = BN / 4;
    constexpr int JT  = WN / 16;   // 2
    constexpr int ASZ = 64 * LDA;
    constexpr int BSZ = 32 * LDB;

    extern __shared__ __nv_bfloat16 smem[];
    __nv_bfloat16* Ah = smem;
    __nv_bfloat16* Al = smem + 2 * ASZ;
    __nv_bfloat16* Bh = smem + 4 * ASZ;
    __nv_bfloat16* Bl = smem + 4 * ASZ + 2 * BSZ;

    const __nv_bfloat16* __restrict__ Wh = g_w1h;
    const __nv_bfloat16* __restrict__ Wl = g_w1l;

    const int tid = threadIdx.x;
    const int wid = tid >> 5;
    const int wm = wid & 1;
    const int wn = wid >> 1;
    const int row0 = blockIdx.x * 64;

    wmma::fragment<wmma::accumulator, 16, 16, 16, float> acc[2][JT];
    #pragma unroll
    for (int i = 0; i < 2; i++)
        #pragma unroll
        for (int j = 0; j < JT; j++) wmma::fill_fragment(acc[i][j], 0.0f);

    const float4 z4 = make_float4(0.f, 0.f, 0.f, 0.f);

    auto ldgA = [&](int k0, float4* pa) {
        #pragma unroll
        for (int p = 0; p < 2; p++) {
            int f = tid + p * 256;
            int r = f >> 3, c = f & 7;
            int gr = row0 + r;
            pa[p] = (gr < n) ? *(const float4*)(X + (size_t)gr * K + k0 + c * 4)
                             : z4;
        }
    };
    auto stsA = [&](int st, const float4* pa) {
        #pragma unroll
        for (int p = 0; p < 2; p++) {
            int f = tid + p * 256;
            int r = f >> 3, c = f & 7;
            float4 v = pa[p];
            __nv_bfloat16 h0 = __float2bfloat16_rn(v.x);
            __nv_bfloat16 h1 = __float2bfloat16_rn(v.y);
            __nv_bfloat16 h2 = __float2bfloat16_rn(v.z);
            __nv_bfloat16 h3 = __float2bfloat16_rn(v.w);
            __nv_bfloat162 hp0 = __nv_bfloat162(h0, h1);
            __nv_bfloat162 hp1 = __nv_bfloat162(h2, h3);
            __nv_bfloat162 lp0 = __nv_bfloat162(
                __float2bfloat16_rn(v.x - __bfloat162float(h0)),
                __float2bfloat16_rn(v.y - __bfloat162float(h1)));
            __nv_bfloat162 lp1 = __nv_bfloat162(
                __float2bfloat16_rn(v.z - __bfloat162float(h2)),
                __float2bfloat16_rn(v.w - __bfloat162float(h3)));
            uint2 hw, lw;
            hw.x = *(uint32_t*)&hp0; hw.y = *(uint32_t*)&hp1;
            lw.x = *(uint32_t*)&lp0; lw.y = *(uint32_t*)&lp1;
            *(uint2*)&Ah[st * ASZ + r * LDA + c * 4] = hw;
            *(uint2*)&Al[st * ASZ + r * LDA + c * 4] = lw;
        }
    };
    auto cpaB = [&](int st, int k0) {
        #pragma unroll
        for (int p = 0; p < 2; p++) {
            int idx = tid + p * 256;
            int r = idx >> 4, c8 = idx & 15;
            cpa16(&Bh[st * BSZ + r * LDB + c8 * 8],
                  Wh + (size_t)(k0 + r) * BN + c8 * 8);
            cpa16(&Bl[st * BSZ + r * LDB + c8 * 8],
                  Wl + (size_t)(k0 + r) * BN + c8 * 8);
        }
        CPA_COMMIT();
    };

    float4 pa[2];
    ldgA(0, pa);
    cpaB(0, 0);
    stsA(0, pa);
    CPA_WAIT0();
    __syncthreads();

    const int T = K >> 5;
    for (int t = 0; t < T; t++) {
        const int cur = t & 1, nxt = cur ^ 1;
        const bool more = (t + 1 < T);
        if (more) {
            cpaB(nxt, (t + 1) << 5);
            ldgA((t + 1) << 5, pa);
        }

        #pragma unroll
        for (int ks = 0; ks < 2; ks++) {
            wmma::fragment<wmma::matrix_a, 16, 16, 16, __nv_bfloat16,
                           wmma::row_major> ah[2], al[2];
            #pragma unroll
            for (int i = 0; i < 2; i++) {
                wmma::load_matrix_sync(ah[i],
                    &Ah[cur * ASZ + (wm * 32 + i * 16) * LDA + ks * 16], LDA);
                wmma::load_matrix_sync(al[i],
                    &Al[cur * ASZ + (wm * 32 + i * 16) * LDA + ks * 16], LDA);
            }
            #pragma unroll
            for (int j = 0; j < JT; j++) {
                wmma::fragment<wmma::matrix_b, 16, 16, 16, __nv_bfloat16,
                               wmma::row_major> bh, bl;
                wmma::load_matrix_sync(bh,
                    &Bh[cur * BSZ + ks * 16 * LDB + wn * WN + j * 16], LDB);
                wmma::load_matrix_sync(bl,
                    &Bl[cur * BSZ + ks * 16 * LDB + wn * WN + j * 16], LDB);
                wmma::mma_sync(acc[0][j], ah[0], bh, acc[0][j]);
                wmma::mma_sync(acc[1][j], ah[1], bh, acc[1][j]);
                wmma::mma_sync(acc[0][j], ah[0], bl, acc[0][j]);
                wmma::mma_sync(acc[1][j], ah[1], bl, acc[1][j]);
                wmma::mma_sync(acc[0][j], al[0], bh, acc[0][j]);
                wmma::mma_sync(acc[1][j], al[1], bh, acc[1][j]);
            }
        }

        if (more) {
            stsA(nxt, pa);
            CPA_WAIT0();
        }
        __syncthreads();
    }

    #pragma unroll
    for (int i = 0; i < 2; i++) {
        int r = row0 + wm * 32 + i * 16;
        #pragma unroll
        for (int j = 0; j < JT; j++) {
            int c = wn * WN + j * 16;
            wmma::store_matrix_sync(&g_h[(size_t)r * BN + c], acc[i][j], BN,
                                    wmma::mem_row_major);
        }
    }
}

// -------------------- GEMM2/3: pre-split bf16 input, all cp.async -----------
// g_h[n,BN] = x[n,128] @ W[K=128,BN]; x given as g_xh/g_xl (rows >= n are
// zero-initialized device memory -> safe). No cvt, no staging registers.
template <int BN>
__global__ void __launch_bounds__(256, 3)
wgemm_pre(int wsel, int n) {
    constexpr int K   = 128;
    constexpr int LDA = 40;
    constexpr int LDB = BN + 8;
    constexpr int WN  = BN / 4;
    constexpr int JT  = WN / 16;   // 2 or 1
    constexpr int ASZ = 64 * LDA;
    constexpr int BSZ = 32 * LDB;

    extern __shared__ __nv_bfloat16 smem[];
    __nv_bfloat16* Ah = smem;
    __nv_bfloat16* Al = smem + 2 * ASZ;
    __nv_bfloat16* Bh = smem + 4 * ASZ;
    __nv_bfloat16* Bl = smem + 4 * ASZ + 2 * BSZ;

    const __nv_bfloat16* __restrict__ Xh = g_xh;
    const __nv_bfloat16* __restrict__ Xl = g_xl;
    const __nv_bfloat16* __restrict__ Wh = (wsel == 1) ? g_w2h : g_w3h;
    const __nv_bfloat16* __restrict__ Wl = (wsel == 1) ? g_w2l : g_w3l;

    const int tid = threadIdx.x;
    const int wid = tid >> 5;
    const int wm = wid & 1;
    const int wn = wid >> 1;
    const int row0 = blockIdx.x * 64;

    wmma::fragment<wmma::accumulator, 16, 16, 16, float> acc[2][JT];
    #pragma unroll
    for (int i = 0; i < 2; i++)
        #pragma unroll
        for (int j = 0; j < JT; j++) wmma::fill_fragment(acc[i][j], 0.0f);

    // A: 64 rows x 32 bf16 = 256 uint4 per buffer; 1 per thread per buffer
    const int ar  = tid >> 2;        // 0..63
    const int ac4 = tid & 3;         // uint4 within row
    auto cpaA = [&](int st, int k0) {
        int gr = row0 + ar;
        cpa16(&Ah[st * ASZ + ar * LDA + ac4 * 8],
              Xh + (size_t)gr * K + k0 + ac4 * 8);
        cpa16(&Al[st * ASZ + ar * LDA + ac4 * 8],
              Xl + (size_t)gr * K + k0 + ac4 * 8);
    };
    auto cpaB = [&](int st, int k0) {
        if (BN == 128) {
            #pragma unroll
            for (int p = 0; p < 2; p++) {
                int idx = tid + p * 256;
                int r = idx >> 4, c8 = idx & 15;
                cpa16(&Bh[st * BSZ + r * LDB + c8 * 8],
                      Wh + (size_t)(k0 + r) * BN + c8 * 8);
                cpa16(&Bl[st * BSZ + r * LDB + c8 * 8],
                      Wl + (size_t)(k0 + r) * BN + c8 * 8);
            }
        } else {
            int r = tid >> 3, c8 = tid & 7;
            cpa16(&Bh[st * BSZ + r * LDB + c8 * 8],
                  Wh + (size_t)(k0 + r) * BN + c8 * 8);
            cpa16(&Bl[st * BSZ + r * LDB + c8 * 8],
                  Wl + (size_t)(k0 + r) * BN + c8 * 8);
        }
    };

    cpaA(0, 0);
    cpaB(0, 0);
    CPA_COMMIT();
    CPA_WAIT0();
    __syncthreads();

    const int T = K >> 5;   // 4
    for (int t = 0; t < T; t++) {
        const int cur = t & 1, nxt = cur ^ 1;
        const bool more = (t + 1 < T);
        if (more) {
            cpaA(nxt, (t + 1) << 5);
            cpaB(nxt, (t + 1) << 5);
            CPA_COMMIT();
        }

        #pragma unroll
        for (int ks = 0; ks < 2; ks++) {
            wmma::fragment<wmma::matrix_a, 16, 16, 16, __nv_bfloat16,
                           wmma::row_major> ah[2], al[2];
            #pragma unroll
            for (int i = 0; i < 2; i++) {
                wmma::load_matrix_sync(ah[i],
                    &Ah[cur * ASZ + (wm * 32 + i * 16) * LDA + ks * 16], LDA);
                wmma::load_matrix_sync(al[i],
                    &Al[cur * ASZ + (wm * 32 + i * 16) * LDA + ks * 16], LDA);
            }
            #pragma unroll
            for (int j = 0; j < JT; j++) {
                wmma::fragment<wmma::matrix_b, 16, 16, 16, __nv_bfloat16,
                               wmma::row_major> bh, bl;
                wmma::load_matrix_sync(bh,
                    &Bh[cur * BSZ + ks * 16 * LDB + wn * WN + j * 16], LDB);
                wmma::load_matrix_sync(bl,
                    &Bl[cur * BSZ + ks * 16 * LDB + wn * WN + j * 16], LDB);
                wmma::mma_sync(acc[0][j], ah[0], bh, acc[0][j]);
                wmma::mma_sync(acc[1][j], ah[1], bh, acc[1][j]);
                wmma::mma_sync(acc[0][j], ah[0], bl, acc[0][j]);
                wmma::mma_sync(acc[1][j], ah[1], bl, acc[1][j]);
                wmma::mma_sync(acc[0][j], al[0], bh, acc[0][j]);
                wmma::mma_sync(acc[1][j], al[1], bh, acc[1][j]);
            }
        }

        if (more) CPA_WAIT0();
        __syncthreads();
    }

    #pragma unroll
    for (int i = 0; i < 2; i++) {
        int r = row0 + wm * 32 + i * 16;
        #pragma unroll
        for (int j = 0; j < JT; j++) {
            int c = wn * WN + j * 16;
            wmma::store_matrix_sync(&g_h[(size_t)r * BN + c], acc[i][j], BN,
                                    wmma::mem_row_major);
        }
    }
}

// -------------------- aggregation: one warp per node, float4 per lane -------
// Emits bf16 hi/lo split directly (same byte count as fp32; GEMM2/3 consume).
__global__ void agg128_relu(const float* __restrict__ bias, int n) {
    int node = (blockIdx.x * blockDim.x + threadIdx.x) >> 5;
    int lane = threadIdx.x & 31;
    if (node >= n) return;
    const float4* __restrict__ h4 = (const float4*)g_h;
    float4 b4 = ((const float4*)bias)[lane];
    float dn = g_dis[node];
    float4 hv = h4[(size_t)node * 32 + lane];
    float4 acc = make_float4(dn * hv.x, dn * hv.y, dn * hv.z, dn * hv.w);

    int j = g_off[node], end = g_off[node + 1];
    for (; j + 3 < end; j += 4) {
        int s0 = g_csr[j],     s1 = g_csr[j + 1];
        int s2 = g_csr[j + 2], s3 = g_csr[j + 3];
        float d0 = g_dis[s0], d1 = g_dis[s1], d2 = g_dis[s2], d3 = g_dis[s3];
        float4 v0 = h4[(size_t)s0 * 32 + lane];
        float4 v1 = h4[(size_t)s1 * 32 + lane];
        float4 v2 = h4[(size_t)s2 * 32 + lane];
        float4 v3 = h4[(size_t)s3 * 32 + lane];
        acc.x = fmaf(d0, v0.x, acc.x); acc.y = fmaf(d0, v0.y, acc.y);
        acc.z = fmaf(d0, v0.z, acc.z); acc.w = fmaf(d0, v0.w, acc.w);
        acc.x = fmaf(d1, v1.x, acc.x); acc.y = fmaf(d1, v1.y, acc.y);
        acc.z = fmaf(d1, v1.z, acc.z); acc.w = fmaf(d1, v1.w, acc.w);
        acc.x = fmaf(d2, v2.x, acc.x); acc.y = fmaf(d2, v2.y, acc.y);
        acc.z = fmaf(d2, v2.z, acc.z); acc.w = fmaf(d2, v2.w, acc.w);
        acc.x = fmaf(d3, v3.x, acc.x); acc.y = fmaf(d3, v3.y, acc.y);
        acc.z = fmaf(d3, v3.z, acc.z); acc.w = fmaf(d3, v3.w, acc.w);
    }
    for (; j < end; ++j) {
        int s0 = g_csr[j];
        float d0 = g_dis[s0];
        float4 v0 = h4[(size_t)s0 * 32 + lane];
        acc.x = fmaf(d0, v0.x, acc.x); acc.y = fmaf(d0, v0.y, acc.y);
        acc.z = fmaf(d0, v0.z, acc.z); acc.w = fmaf(d0, v0.w, acc.w);
    }
    float r0 = fmaxf(fmaf(dn, acc.x, b4.x), 0.f);
    float r1 = fmaxf(fmaf(dn, acc.y, b4.y), 0.f);
    float r2 = fmaxf(fmaf(dn, acc.z, b4.z), 0.f);
    float r3 = fmaxf(fmaf(dn, acc.w, b4.w), 0.f);
    // split into bf16 hi + lo
    __nv_bfloat16 h0 = __float2bfloat16_rn(r0);
    __nv_bfloat16 h1 = __float2bfloat16_rn(r1);
    __nv_bfloat16 h2 = __float2bfloat16_rn(r2);
    __nv_bfloat16 h3 = __float2bfloat16_rn(r3);
    __nv_bfloat162 hp0 = __nv_bfloat162(h0, h1);
    __nv_bfloat162 hp1 = __nv_bfloat162(h2, h3);
    __nv_bfloat162 lp0 = __nv_bfloat162(
        __float2bfloat16_rn(r0 - __bfloat162float(h0)),
        __float2bfloat16_rn(r1 - __bfloat162float(h1)));
    __nv_bfloat162 lp1 = __nv_bfloat162(
        __float2bfloat16_rn(r2 - __bfloat162float(h2)),
        __float2bfloat16_rn(r3 - __bfloat162float(h3)));
    uint2 hw, lw;
    hw.x = *(uint32_t*)&hp0; hw.y = *(uint32_t*)&hp1;
    lw.x = *(uint32_t*)&lp0; lw.y = *(uint32_t*)&lp1;
    ((uint2*)g_xh)[(size_t)node * 32 + lane] = hw;
    ((uint2*)g_xl)[(size_t)node * 32 + lane] = lw;
}

// layer-3 agg + log_softmax: one warp per node, float2 per lane (64 feats)
__global__ void agg64_lsm(const float* __restrict__ bias,
                          float* __restrict__ out, int n) {
    int node = (blockIdx.x * blockDim.x + threadIdx.x) >> 5;
    int lane = threadIdx.x & 31;
    if (node >= n) return;
    const float2* __restrict__ h2 = (const float2*)g_h;
    float2 b2 = ((const float2*)bias)[lane];
    float dn = g_dis[node];
    float2 hv = h2[(size_t)node * 32 + lane];
    float ax = dn * hv.x, ay = dn * hv.y;

    int j = g_off[node], end = g_off[node + 1];
    for (; j + 3 < end; j += 4) {
        int s0 = g_csr[j],     s1 = g_csr[j + 1];
        int s2 = g_csr[j + 2], s3 = g_csr[j + 3];
        float d0 = g_dis[s0], d1 = g_dis[s1], d2 = g_dis[s2], d3 = g_dis[s3];
        float2 v0 = h2[(size_t)s0 * 32 + lane];
        float2 v1 = h2[(size_t)s1 * 32 + lane];
        float2 v2 = h2[(size_t)s2 * 32 + lane];
        float2 v3 = h2[(size_t)s3 * 32 + lane];
        ax = fmaf(d0, v0.x, ax); ay = fmaf(d0, v0.y, ay);
        ax = fmaf(d1, v1.x, ax); ay = fmaf(d1, v1.y, ay);
        ax = fmaf(d2, v2.x, ax); ay = fmaf(d2, v2.y, ay);
        ax = fmaf(d3, v3.x, ax); ay = fmaf(d3, v3.y, ay);
    }
    for (; j < end; ++j) {
        int s0 = g_csr[j];
        float d0 = g_dis[s0];
        float2 v0 = h2[(size_t)s0 * 32 + lane];
        ax = fmaf(d0, v0.x, ax); ay = fmaf(d0, v0.y, ay);
    }
    float v0 = fmaf(dn, ax, b2.x);
    float v1 = fmaf(dn, ay, b2.y);

    float m = fmaxf(v0, v1);
    #pragma unroll
    for (int o = 16; o; o >>= 1) m = fmaxf(m, __shfl_xor_sync(0xffffffffu, m, o));
    float s = expf(v0 - m) + expf(v1 - m);
    #pragma unroll
    for (int o = 16; o; o >>= 1) s += __shfl_xor_sync(0xffffffffu, s, o);
    float l = m + logf(s);
    float2 r = make_float2(v0 - l, v1 - l);
    ((float2*)out)[(size_t)node * 32 + lane] = r;
}

// -------------------- launch --------------------
extern "C" void kernel_launch(void* const* d_in, const int* in_sizes, int n_in,
                              void* d_out, int out_size) {
    const float* feats = (const float*)d_in[0];
    const int*   adj   = (const int*)d_in[1];     // int32 (jax x64 disabled)
    const float* W1    = (const float*)d_in[2];
    const float* b1    = (const float*)d_in[3];
    const float* W2    = (const float*)d_in[4];
    const float* b2    = (const float*)d_in[5];
    const float* W3    = (const float*)d_in[6];
    const float* b3    = (const float*)d_in[7];
    float*       out   = (float*)d_out;

    const int N = in_sizes[0] / IN_DIM;
    const int E = in_sizes[1] / 2;
    const int* src = adj;
    const int* dst = adj + E;
    const int nb = (N + SCAN_BLK - 1) / SCAN_BLK;
    const int gB = (N + 63) / 64;

    const int smem128 = (4 * 64 * 40 + 4 * 32 * 136) * 2;  // 55296 B
    const int smem64  = (4 * 64 * 40 + 4 * 32 * 72) * 2;   // 38912 B
    cudaFuncSetAttribute(wgemm1, cudaFuncAttributeMaxDynamicSharedMemorySize, smem128);
    cudaFuncSetAttribute(wgemm_pre<128>, cudaFuncAttributeMaxDynamicSharedMemorySize, smem128);
    cudaFuncSetAttribute(wgemm_pre<64>,  cudaFuncAttributeMaxDynamicSharedMemorySize, smem64);

    static cudaStream_t s2 = nullptr;
    static cudaEvent_t evFork = nullptr, evJoin = nullptr;
    if (s2 == nullptr) {
        cudaStreamCreateWithFlags(&s2, cudaStreamNonBlocking);
        cudaEventCreateWithFlags(&evFork, cudaEventDisableTiming);
        cudaEventCreateWithFlags(&evJoin, cudaEventDisableTiming);
    }

    // ---- launch 1: W1 split (needed by GEMM1) ----
    wsplit<<<(IN_DIM * HID + 255) / 256, 256>>>(W1, IN_DIM * HID, 0);
    // ---- fork side stream: W2/W3 splits + graph preprocessing ----
    cudaEventRecord(evFork, 0);
    cudaStreamWaitEvent(s2, evFork, 0);
    wsplit<<<(HID * HID + 255) / 256, 256, 0, s2>>>(W2, HID * HID, 1);   // 2
    wsplit<<<(HID * 64 + 255) / 256, 256, 0, s2>>>(W3, HID * 64, 2);     // 3
    // ---- launch 4 (profiled slot): GEMM1 on main stream ----
    wgemm1<<<gB, 256, smem128>>>(feats, N, IN_DIM);

    init_deg<<<(N + 255) / 256, 256, 0, s2>>>(N);
    count_deg<<<(E + 255) / 256, 256, 0, s2>>>(dst, E, N);
    scan_partial<<<nb, SCAN_BLK, 0, s2>>>(N);
    scan_bsum<<<1, 64, 0, s2>>>(nb, N);
    add_off_dis<<<(N + 255) / 256, 256, 0, s2>>>(N);
    fill_csr<<<(E + 255) / 256, 256, 0, s2>>>(src, dst, E, N);
    cudaEventRecord(evJoin, s2);
    cudaStreamWaitEvent(0, evJoin, 0);   // join before aggregation

    // ---- layers (main stream) ----
    agg128_relu<<<(N + 7) / 8, 256>>>(b1, N);
    wgemm_pre<128><<<gB, 256, smem128>>>(1, N);
    agg128_relu<<<(N + 7) / 8, 256>>>(b2, N);
    wgemm_pre<64><<<gB, 256, smem64>>>(2, N);
    agg64_lsm<<<(N + 7) / 8, 256>>>(b3, out, N);
}